// round 17
// baseline (speedup 1.0000x reference)
#include <cuda_runtime.h>
#include <cstdint>

// Problem constants
#define T_STEPS 8192
#define D_INP   512
#define HDIM    768      // H
#define G3      2304     // 3*H
#define RTOT    4608     // 2 dirs * 3H
#define DH2     1536     // 2*H
#define GCTA    32       // CTAs per (layer,dir) group
#define NWARP   24       // GRU units per CTA (one warp each); 32*24 = 768
#define NTHR    768
#define NWORK   20       // GEMM worker CTAs
#define NTM     36       // col tiles (4608/128)
#define NTT     64       // row tiles (8192/128)
#define NT0     (NTM * NTT)      // Gi0 tiles
#define NT1     (NTM * NTT)      // Gi1 tiles
#define SEQ_SMEM ((HDIM + NWARP * HDIM) * 4)   // h_sh + n-rows = 76800 B

typedef unsigned long long ull;

// ---------------- scratch (device globals; no allocation allowed) -------------
__device__ float g_Gi0[(size_t)T_STEPS * RTOT];
__device__ float g_Gi1[(size_t)T_STEPS * RTOT];
__device__ float g_H0[(size_t)(T_STEPS + 1) * DH2];    // plain h (workers + fc)
__device__ float g_H1[(size_t)(T_STEPS + 1) * DH2];
__device__ ull   g_Ht[2][(size_t)(T_STEPS + 1) * DH2]; // tagged (value, epoch*T+t)
__device__ unsigned g_cnt[2][64];   // [layer][dir*32] step counters (worker gating)
__device__ unsigned g_blk[2][NTT];  // finished Gi tiles per t-row
__device__ unsigned g_q;            // worker tile queue head
__device__ unsigned g_epoch;        // launch epoch (persists; ++ per launch)

// ---------------- helpers ------------------------------------------------------
__device__ __forceinline__ ull fma2(ull a, ull b, ull c) {
    ull d;
    asm("fma.rn.f32x2 %0,%1,%2,%3;" : "=l"(d) : "l"(a), "l"(b), "l"(c));
    return d;
}
__device__ __forceinline__ ull pack2(float x, float y) {
    ull r;
    asm("mov.b64 %0,{%1,%2};" : "=l"(r) : "f"(x), "f"(y));
    return r;
}
__device__ __forceinline__ float2 unpack2(ull v) {
    float2 f;
    asm("mov.b64 {%0,%1},%2;" : "=f"(f.x), "=f"(f.y) : "l"(v));
    return f;
}
__device__ __forceinline__ unsigned ldrelax(const unsigned* p) {
    unsigned v;
    asm volatile("ld.relaxed.gpu.global.u32 %0,[%1];" : "=r"(v) : "l"(p));
    return v;
}
__device__ __forceinline__ ull ldrelax64(const ull* p) {
    ull v;
    asm volatile("ld.relaxed.gpu.global.b64 %0,[%1];" : "=l"(v) : "l"(p));
    return v;
}
__device__ __forceinline__ void strelax64(ull* p, ull v) {
    asm volatile("st.relaxed.gpu.global.b64 [%0],%1;" :: "l"(p), "l"(v) : "memory");
}
__device__ __forceinline__ void fence_acqrel() {
    asm volatile("fence.acq_rel.gpu;" ::: "memory");
}
__device__ __forceinline__ void red_release(unsigned* p) {
    asm volatile("red.release.gpu.global.add.u32 [%0],%1;" :: "l"(p), "r"(1u) : "memory");
}
__device__ __forceinline__ void barx(int id, int n) {
    asm volatile("bar.sync %0,%1;" :: "r"(id), "r"(n) : "memory");
}

// ---------------- init ---------------------------------------------------------
__global__ void init_kernel(const float* __restrict__ h0) {
    int j = blockIdx.x * blockDim.x + threadIdx.x;
    if (j < DH2) {
        g_H0[j] = h0[j];          // layer0 dirs = rows 0,1
        g_H1[j] = h0[DH2 + j];    // layer1 dirs = rows 2,3
    }
    if (j < 128) ((unsigned*)g_cnt)[j] = 0u;
    else if (j < 128 + 2 * NTT) ((unsigned*)g_blk)[j - 128] = 0u;
    else if (j == 300) g_q = 0u;
    else if (j == 301) g_epoch = g_epoch + 1u;   // epoch tag base (never reset)
}

// ---------------- sequential GRU chain: one (layer, dir) unit-warp CTA --------
// 24 warps = 24 GRU units. r,z weight rows in registers (packed f32x2);
// n row in dynamic shared memory. Hidden handoff via tagged 8B words: owner
// stores (value, tag) with one relaxed b64; consumer warps 0-1 poll tags and
// stage values directly (data travels WITH the sync — one L2 round trip).
__device__ __forceinline__ void seq_pass(
    int layer, int d, int g,
    const float* __restrict__ Whh, const float* __restrict__ bhh,
    float* smem)
{
    const float* Gi = layer ? g_Gi1 : g_Gi0;
    float* Hs = layer ? g_H1 : g_H0;
    ull* Ht = g_Ht[layer];
    unsigned* cnt = &g_cnt[layer][d * 32];
    const unsigned* blk = g_blk[layer];

    float* h_sh = smem;               // HDIM floats
    float* nsh  = smem + HDIM;        // NWARP * HDIM floats

    const int warp = threadIdx.x >> 5;
    const int lane = threadIdx.x & 31;
    const int i = g * NWARP + warp;   // hidden index within direction
    const int u = d * HDIM + i;

    // r,z rows in registers; n row into shared.
    ull wr[12], wz[12];
    {
        const float* base = Whh + (size_t)d * G3 * HDIM;
        const ull* r64 = reinterpret_cast<const ull*>(base + (size_t)i * HDIM);
        const ull* z64 = reinterpret_cast<const ull*>(base + (size_t)(HDIM + i) * HDIM);
#pragma unroll
        for (int m = 0; m < 12; m++) {
            int p = lane + 32 * m;
            wr[m] = r64[p]; wz[m] = z64[p];
        }
        const float4* nsrc = reinterpret_cast<const float4*>(base + (size_t)(2 * HDIM + i) * HDIM);
        float4* ndst = reinterpret_cast<float4*>(nsh + warp * HDIM);
#pragma unroll
        for (int q = 0; q < 6; q++) ndst[q * 32 + lane] = nsrc[q * 32 + lane];
    }
    const float br = bhh[d * G3 + i];
    const float bz = bhh[d * G3 + HDIM + i];
    const float bn = bhh[d * G3 + 2 * HDIM + i];
    const unsigned tagbase = g_epoch * (unsigned)(T_STEPS + 1);

    // stage h row 0 (seeded by init_kernel)
    h_sh[threadIdx.x] = __ldcg(Hs + d * HDIM + threadIdx.x);
    __syncthreads();
    float hprev = h_sh[i];

    // gate: first Gi tile row must exist before the step-0 prefetch.
    if (threadIdx.x == 0) {
        while (ldrelax(&blk[0]) < (unsigned)NTM) __nanosleep(128);
        fence_acqrel();
    }
    __syncthreads();

    float gr = 0.f, gz = 0.f, gn = 0.f;
    if (lane == 0) {
        const float* gp = Gi + d * G3 + i;
        gr = __ldg(gp); gz = __ldg(gp + HDIM); gn = __ldg(gp + 2 * HDIM);
    }

    const ull* n64 = reinterpret_cast<const ull*>(nsh + warp * HDIM);

    for (int t = 0; t < T_STEPS; t++) {
        const ull* h64 = reinterpret_cast<const ull*>(h_sh);
        ull ar = 0ull, az = 0ull, an = 0ull;
#pragma unroll
        for (int m = 0; m < 12; m++) {
            ull hv = h64[lane + 32 * m];
            ar = fma2(wr[m], hv, ar);
            az = fma2(wz[m], hv, az);
            an = fma2(n64[lane + 32 * m], hv, an);
        }
        float2 fr = unpack2(ar), fz = unpack2(az), fn = unpack2(an);
        float sr = fr.x + fr.y, sz = fz.x + fz.y, sn = fn.x + fn.y;
#pragma unroll
        for (int off = 16; off > 0; off >>= 1) {
            sr += __shfl_down_sync(0xffffffffu, sr, off);
            sz += __shfl_down_sync(0xffffffffu, sz, off);
            sn += __shfl_down_sync(0xffffffffu, sn, off);
        }

        // prefetch next step's Gi (tile row availability gated at barriers).
        float gr_n = 0.f, gz_n = 0.f, gn_n = 0.f;
        if (lane == 0 && t + 1 < T_STEPS) {
            const float* gp = Gi + (size_t)(t + 1) * RTOT + d * G3 + i;
            gr_n = __ldg(gp); gz_n = __ldg(gp + HDIM); gn_n = __ldg(gp + 2 * HDIM);
        }

        if (lane == 0) {
            float r = 1.f / (1.f + __expf(-(gr + sr + br)));
            float z = 1.f / (1.f + __expf(-(gz + sz + bz)));
            float n = tanhf(gn + r * (sn + bn));
            float hnew = (1.f - z) * n + z * hprev;
            hprev = hnew;
            // tagged word: data + readiness in ONE atomic 8B relaxed store.
            ull w = ((ull)(tagbase + (unsigned)(t + 1)) << 32) |
                    (ull)__float_as_uint(hnew);
            strelax64(&Ht[(size_t)(t + 1) * DH2 + u], w);
            __stcg(&Hs[(size_t)(t + 1) * DH2 + u], hnew);   // plain copy (workers/fc)
        }
        gr = gr_n; gz = gz_n; gn = gn_n;

        __syncthreads();                       // owners' stores issued

        if (t + 1 < T_STEPS) {
            if (threadIdx.x == 0 && layer == 0)
                red_release(cnt);              // worker progress signal
            if (threadIdx.x < 64) {
                // lane 0: gate the Gi tile row needed by NEXT step's prefetch.
                if (threadIdx.x == 0 && ((t + 2) & 127) == 0 && t + 2 < T_STEPS) {
                    const unsigned* bp = &blk[(t + 2) >> 7];
                    while (ldrelax(bp) < (unsigned)NTM) __nanosleep(128);
                    fence_acqrel();
                }
                // tag-poll h row t+1: 64 lanes x 12 words, data stages as it lands.
                const ull* src = Ht + (size_t)(t + 1) * DH2 + d * HDIM + threadIdx.x;
                const unsigned want = tagbase + (unsigned)(t + 1);
                unsigned pend = 0xFFFu;
                while (__any_sync(0xffffffffu, pend != 0u)) {
#pragma unroll
                    for (int q = 0; q < 12; q++) {
                        if (pend & (1u << q)) {
                            ull v = ldrelax64(src + q * 64);
                            if ((unsigned)(v >> 32) == want) {
                                h_sh[q * 64 + threadIdx.x] =
                                    __uint_as_float((unsigned)v);
                                pend &= ~(1u << q);
                            }
                        }
                    }
                }
            }
            __syncthreads();                   // h_sh row t+1 ready
        } else {
            if (threadIdx.x == 0 && layer == 0) red_release(cnt);
            __syncthreads();
        }
    }
}

// ---------------- GEMM worker (512 active threads) -----------------------------
// Queue of Gi0 tiles (K=512, ungated) then Gi1 tiles (K=1536, gated on layer-0).
__device__ __forceinline__ void worker_gemm(
    const float* __restrict__ x,
    const float* __restrict__ wih0, const float* __restrict__ bih0,
    const float* __restrict__ wih1, const float* __restrict__ bih1,
    float* smem, unsigned* s_n)
{
    const int tid = threadIdx.x;          // 0..511
    const int tx = tid & 31, ty = tid >> 5;       // 32 m-thr x 16 t-thr
    const int r = tid >> 2, c4 = (tid & 3) * 4;   // staging slot (1 float4)
    float* As = smem;                     // 2 x 2048 floats
    float* Bs = smem + 4096;              // 2 x 2048 floats

    for (;;) {
        if (tid == 0) *s_n = atomicAdd(&g_q, 1u);
        barx(3, 512);
        unsigned n = *s_n;
        barx(3, 512);
        if (n >= NT0 + NT1) break;

        const int which = (n >= NT0) ? 1 : 0;
        const int tau = which ? (int)n - NT0 : (int)n;
        const int trow = tau / NTM, mcol = tau % NTM;
        const int K = which ? DH2 : D_INP;

        if (which && tid == 0) {
            // Gi1 tile needs h0 rows trow*128+1 .. +128.
            unsigned tgt = (unsigned)(trow + 1) * 128u * GCTA;
            while (ldrelax(&g_cnt[0][0]) < tgt || ldrelax(&g_cnt[0][32]) < tgt)
                __nanosleep(512);
            fence_acqrel();
        }
        barx(3, 512);

        const float* Ab = which ? (g_H0 + ((size_t)trow * 128 + 1) * DH2)
                                : (x + (size_t)trow * 128 * D_INP);
        const float* Bb = (which ? wih1 : wih0) + (size_t)mcol * 128 * K;
        const float* bias = (which ? bih1 : bih0) + mcol * 128 + tx * 4;
        float* Cb = (which ? g_Gi1 : g_Gi0) + (size_t)trow * 128 * RTOT + mcol * 128;

        ull acc2[8][2];
#pragma unroll
        for (int a = 0; a < 8; a++) { acc2[a][0] = 0ull; acc2[a][1] = 0ull; }

        float4 va = *reinterpret_cast<const float4*>(Ab + (size_t)r * K + c4);
        float4 vb = *reinterpret_cast<const float4*>(Bb + (size_t)r * K + c4);
        As[(c4 + 0) * 128 + r] = va.x; As[(c4 + 1) * 128 + r] = va.y;
        As[(c4 + 2) * 128 + r] = va.z; As[(c4 + 3) * 128 + r] = va.w;
        Bs[(c4 + 0) * 128 + r] = vb.x; Bs[(c4 + 1) * 128 + r] = vb.y;
        Bs[(c4 + 2) * 128 + r] = vb.z; Bs[(c4 + 3) * 128 + r] = vb.w;
        barx(3, 512);

        int buf = 0;
        for (int k0 = 0; k0 < K; k0 += 16) {
            const bool more = (k0 + 16 < K);
            if (more) {
                va = *reinterpret_cast<const float4*>(Ab + (size_t)r * K + k0 + 16 + c4);
                vb = *reinterpret_cast<const float4*>(Bb + (size_t)r * K + k0 + 16 + c4);
            }
            const float* Ap = As + buf * 2048;
            const float* Bp = Bs + buf * 2048;
#pragma unroll
            for (int kk = 0; kk < 16; kk++) {
                float4 a0 = *reinterpret_cast<const float4*>(Ap + kk * 128 + ty * 8);
                float4 a1 = *reinterpret_cast<const float4*>(Ap + kk * 128 + ty * 8 + 4);
                float4 b  = *reinterpret_cast<const float4*>(Bp + kk * 128 + tx * 4);
                ull rb0 = pack2(b.x, b.y), rb1 = pack2(b.z, b.w);
                float ra[8] = {a0.x, a0.y, a0.z, a0.w, a1.x, a1.y, a1.z, a1.w};
#pragma unroll
                for (int a = 0; a < 8; a++) {
                    ull ra2 = pack2(ra[a], ra[a]);
                    acc2[a][0] = fma2(ra2, rb0, acc2[a][0]);
                    acc2[a][1] = fma2(ra2, rb1, acc2[a][1]);
                }
            }
            if (more) {
                float* An = As + (buf ^ 1) * 2048;
                float* Bn = Bs + (buf ^ 1) * 2048;
                An[(c4 + 0) * 128 + r] = va.x; An[(c4 + 1) * 128 + r] = va.y;
                An[(c4 + 2) * 128 + r] = va.z; An[(c4 + 3) * 128 + r] = va.w;
                Bn[(c4 + 0) * 128 + r] = vb.x; Bn[(c4 + 1) * 128 + r] = vb.y;
                Bn[(c4 + 2) * 128 + r] = vb.z; Bn[(c4 + 3) * 128 + r] = vb.w;
                barx(3, 512);
            }
            buf ^= 1;
        }

        float4 bv = *reinterpret_cast<const float4*>(bias);
#pragma unroll
        for (int a = 0; a < 8; a++) {
            float2 f0 = unpack2(acc2[a][0]), f1 = unpack2(acc2[a][1]);
            *reinterpret_cast<float4*>(Cb + (size_t)(ty * 8 + a) * RTOT + tx * 4) =
                make_float4(f0.x + bv.x, f0.y + bv.y, f1.x + bv.z, f1.y + bv.w);
        }
        barx(3, 512);
        if (tid == 0) red_release(&g_blk[which][trow]);
        barx(3, 512);
    }
}

// ---------------- fused pass: both layers + workers, one kernel ----------------
__global__ __launch_bounds__(NTHR, 1) void pass_kernel(
    const float* __restrict__ x,
    const float* __restrict__ w_hh0, const float* __restrict__ b_hh0,
    const float* __restrict__ w_hh1, const float* __restrict__ b_hh1,
    const float* __restrict__ w_ih0, const float* __restrict__ b_ih0,
    const float* __restrict__ w_ih1, const float* __restrict__ b_ih1)
{
    extern __shared__ float smem[];
    __shared__ unsigned s_n;
    const int bid = blockIdx.x;

    if (bid < 128) {
        const int layer = bid >> 6;        // 0..63 -> layer0, 64..127 -> layer1
        const int lb = bid & 63;
        seq_pass(layer, lb & 1, lb >> 1,
                 layer ? w_hh1 : w_hh0, layer ? b_hh1 : b_hh0, smem);
    } else {
        if (threadIdx.x >= 512) return;    // workers use 512 threads
        worker_gemm(x, w_ih0, b_ih0, w_ih1, b_ih1, smem, &s_n);
    }
}

// ---------------- final FC + sigmoid ------------------------------------------
__global__ void fc_kernel(const float* __restrict__ fcw,
                          const float* __restrict__ fcb,
                          float* __restrict__ out)
{
    int gw = (blockIdx.x * blockDim.x + threadIdx.x) >> 5;
    int lane = threadIdx.x & 31;
    if (gw >= 256) return;
    const float* h = g_H1 + (size_t)T_STEPS * DH2;
    float acc = 0.f;
    for (int k = lane; k < DH2; k += 32)
        acc += fcw[(size_t)gw * DH2 + k] * h[k];
#pragma unroll
    for (int off = 16; off > 0; off >>= 1)
        acc += __shfl_down_sync(0xffffffffu, acc, off);
    if (lane == 0)
        out[gw] = 1.f / (1.f + __expf(-(acc + fcb[gw])));
}

// ---------------- launch ------------------------------------------------------
extern "C" void kernel_launch(void* const* d_in, const int* in_sizes, int n_in,
                              void* d_out, int out_size)
{
    const float* x     = (const float*)d_in[0];
    const float* h0    = (const float*)d_in[1];
    const float* w_ih0 = (const float*)d_in[2];
    const float* w_hh0 = (const float*)d_in[3];
    const float* b_ih0 = (const float*)d_in[4];
    const float* b_hh0 = (const float*)d_in[5];
    const float* w_ih1 = (const float*)d_in[6];
    const float* w_hh1 = (const float*)d_in[7];
    const float* b_ih1 = (const float*)d_in[8];
    const float* b_hh1 = (const float*)d_in[9];
    const float* fc_w  = (const float*)d_in[10];
    const float* fc_b  = (const float*)d_in[11];
    float* out = (float*)d_out;

    (void)in_sizes; (void)n_in; (void)out_size;

    cudaFuncSetAttribute(pass_kernel,
                         cudaFuncAttributeMaxDynamicSharedMemorySize, SEQ_SMEM);

    init_kernel<<<6, 256>>>(h0);

    // Single persistent kernel: Gi0 + Gi1 produced by 20 worker CTAs,
    // both GRU layers run concurrently (layer 1 trails ~128 steps),
    // hidden-state handoff via tagged 8B words (sync carries the data).
    pass_kernel<<<128 + NWORK, NTHR, SEQ_SMEM>>>(
        x, w_hh0, b_hh0, w_hh1, b_hh1, w_ih0, b_ih0, w_ih1, b_ih1);

    fc_kernel<<<32, 256>>>(fc_w, fc_b, out);
}